// round 3
// baseline (speedup 1.0000x reference)
#include <cuda_runtime.h>
#include <cstdint>

#define NN 4096

__device__ __align__(128) float g_x[NN*66];
__device__ __align__(128) float g_h[4*NN*72];
__device__ __align__(128) float g_f1[4*NN];
__device__ __align__(128) float g_f2[4*NN];
__device__ __align__(128) float g_mx[4*NN];
__device__ __align__(128) float g_hcat[NN*264];
__device__ __align__(128) float g_sub[NN*66];
__device__ __align__(128) float g_u[NN*64];
__device__ __align__(128) unsigned g_mask[NN*128];

__device__ __forceinline__ void fma2(unsigned long long& d, unsigned long long a, unsigned long long b){
    asm("fma.rn.f32x2 %0, %1, %2, %0;" : "+l"(d) : "l"(a), "l"(b));
}
__device__ __forceinline__ unsigned long long dup2(float v){
    unsigned long long r; asm("mov.b64 %0, {%1, %1};" : "=l"(r) : "f"(v)); return r;
}
__device__ __forceinline__ float2 up2(unsigned long long v){
    float2 r; asm("mov.b64 {%0, %1}, %2;" : "=f"(r.x), "=f"(r.y) : "l"(v)); return r;
}

__global__ void __launch_bounds__(256) pack_mask_kernel(const int* __restrict__ adj, unsigned* __restrict__ mask){
    int idx = blockIdx.x*256 + threadIdx.x;
    const int4* p = (const int4*)(adj + (size_t)idx*32);
    unsigned m = 0;
#pragma unroll
    for (int q = 0; q < 8; q++){
        int4 v = p[q];
        m |= (v.x>0?1u:0u)<<(q*4+0); m |= (v.y>0?1u:0u)<<(q*4+1);
        m |= (v.z>0?1u:0u)<<(q*4+2); m |= (v.w>0?1u:0u)<<(q*4+3);
    }
    mask[idx] = m;
}

__global__ void __launch_bounds__(256) build_x1_kernel(const float* __restrict__ inputs, const float* __restrict__ hx, float* __restrict__ x){
    int idx = blockIdx.x*256 + threadIdx.x;
    if (idx >= NN*66) return;
    int i = idx/66, c = idx - i*66;
    x[idx] = (c < 2) ? inputs[i*2+c] : hx[i*64 + c-2];
}

// h = x @ W per head (+ f1=h@a1, f2=h@a2). grid (N/64, nhead), block 256.
__global__ void __launch_bounds__(256) proj_kernel(const float* __restrict__ x, int Din,
    const float* __restrict__ W, const float* __restrict__ a1, const float* __restrict__ a2,
    float* __restrict__ ho, float* __restrict__ f1o, float* __restrict__ f2o)
{
    __shared__ float Ws[66*66];
    __shared__ float xs[64*67];
    const int head = blockIdx.y;
    const int row0 = blockIdx.x*64;
    const int tid = threadIdx.x;
    W += (size_t)head*Din*66; a1 += head*66; a2 += head*66;
    const int r = tid>>2, part = tid&3;
    const int c0 = (part<2) ? part*17 : 34 + (part-2)*16;
    const int cnt = (part<2) ? 17 : 16;
    float acc[17];
#pragma unroll
    for (int c = 0; c < 17; c++) acc[c] = 0.f;
    for (int k0 = 0; k0 < Din; k0 += 66){
        __syncthreads();
        for (int idx = tid; idx < 66*66; idx += 256) Ws[idx] = W[(size_t)k0*66 + idx];
        for (int idx = tid; idx < 64*66; idx += 256){
            int rr = idx/66, kk = idx - rr*66;
            xs[rr*67+kk] = x[(size_t)(row0+rr)*Din + k0 + kk];
        }
        __syncthreads();
        for (int kk = 0; kk < 66; kk++){
            float xv = xs[r*67+kk];
            const float* wr = Ws + kk*66 + c0;
#pragma unroll
            for (int c = 0; c < 17; c++) if (c < cnt) acc[c] += xv*wr[c];
        }
    }
    float p1 = 0.f, p2 = 0.f;
#pragma unroll
    for (int c = 0; c < 17; c++) if (c < cnt){ p1 += acc[c]*a1[c0+c]; p2 += acc[c]*a2[c0+c]; }
    p1 += __shfl_xor_sync(~0u, p1, 1); p1 += __shfl_xor_sync(~0u, p1, 2);
    p2 += __shfl_xor_sync(~0u, p2, 1); p2 += __shfl_xor_sync(~0u, p2, 2);
    int row = row0 + r;
    if (part == 0){ f1o[head*NN+row] = p1; f2o[head*NN+row] = p2; }
    float* hr = ho + (size_t)(head*NN+row)*72;
#pragma unroll
    for (int c = 0; c < 17; c++) if (c < cnt) hr[c0+c] = acc[c];
    if (part == 3){
#pragma unroll
        for (int c = 66; c < 72; c++) hr[c] = 0.f;
    }
}

// masked row-max of f2 per head. one warp per row.
__global__ void __launch_bounds__(256) rowmax_kernel(const float* __restrict__ f2b,
    const unsigned* __restrict__ mask, float* __restrict__ mxo, int NH)
{
    int row = blockIdx.x*8 + (threadIdx.x>>5);
    int lane = threadIdx.x & 31;
    float m0=-3e38f, m1=-3e38f, m2=-3e38f, m3=-3e38f;
    for (int k = 0; k < 128; k++){
        unsigned w = mask[(size_t)row*128 + k];
        if ((w>>lane)&1u){
            int j = k*32 + lane;
            m0 = fmaxf(m0, f2b[j]);
            if (NH > 1){
                m1 = fmaxf(m1, f2b[NN+j]);
                m2 = fmaxf(m2, f2b[2*NN+j]);
                m3 = fmaxf(m3, f2b[3*NN+j]);
            }
        }
    }
    float mm[4] = {m0,m1,m2,m3};
#pragma unroll
    for (int h = 0; h < 4; h++){
        if (h >= NH) break;
        float v = mm[h];
#pragma unroll
        for (int s = 16; s; s >>= 1) v = fmaxf(v, __shfl_xor_sync(~0u, v, s));
        if (lane == 0) mxo[h*NN+row] = v;
    }
}

// fused masked softmax-attention aggregation. 64 rows/block, 256 threads, head = blockIdx.z.
__global__ void __launch_bounds__(256) agg_kernel(const float* __restrict__ hb,
    const float* __restrict__ f1b, const float* __restrict__ f2b, const float* __restrict__ mxb,
    const unsigned* __restrict__ mask, float* __restrict__ outp, int os)
{
    __shared__ float h_s[64*80];
    __shared__ float w_s[64*66];
    __shared__ float f2_s[64];
    __shared__ float den_s[64];
    const int head = blockIdx.z;
    const int row0 = blockIdx.x*64;
    const int tid = threadIdx.x;
    const float* hsrc = hb + (size_t)head*NN*72;
    const int ar = tid&63, jh = tid>>6;          // phase A: row ar, j-range jh*16..+16
    const float f1r = f1b[head*NN + row0 + ar];
    float Mr = f1r + mxb[head*NN + row0 + ar];
    Mr = fmaxf(Mr, 0.2f*Mr);
    const int rg = tid>>3, cq = tid&7;           // phase B: rows 2rg,2rg+1; cols cq*10..+10
    unsigned long long acc0[5] = {0,0,0,0,0};
    unsigned long long acc1[5] = {0,0,0,0,0};
    for (int idx = tid; idx < 128; idx += 256){
        int jr = idx>>1, c = 72 + (idx&1)*4;
        *(float4*)&h_s[jr*80+c] = make_float4(0.f,0.f,0.f,0.f);
    }
    for (int jt = 0; jt < 64; jt++){
        __syncthreads();
        for (int idx = tid; idx < 64*18; idx += 256){
            int jr = idx/18, c4 = idx - jr*18;
            float4 v = *(const float4*)&hsrc[(size_t)(jt*64+jr)*72 + c4*4];
            if (c4 == 16) v.z = 1.0f;            // ones column at col 66 -> denominator
            *(float4*)&h_s[jr*80 + c4*4] = v;
        }
        if (tid < 64) f2_s[tid] = f2b[head*NN + jt*64 + tid];
        __syncthreads();
        {
            unsigned mw = mask[(size_t)(row0+ar)*128 + jt*2 + (jh>>1)];
            int bs = (jh&1)*16;
#pragma unroll
            for (int k = 0; k < 16; k++){
                int j = jh*16 + k;
                float e = f1r + f2_s[j];
                e = fmaxf(e, 0.2f*e);
                w_s[j*66 + ar] = ((mw>>(bs+k))&1u) ? __expf(e - Mr) : 0.f;
            }
        }
        __syncthreads();
#pragma unroll 4
        for (int j = 0; j < 64; j++){
            float2 wp = *(const float2*)&w_s[j*66 + 2*rg];
            unsigned long long w0 = dup2(wp.x), w1 = dup2(wp.y);
            const unsigned long long* hp = (const unsigned long long*)(h_s + j*80 + cq*10);
            fma2(acc0[0], w0, hp[0]); fma2(acc1[0], w1, hp[0]);
            fma2(acc0[1], w0, hp[1]); fma2(acc1[1], w1, hp[1]);
            fma2(acc0[2], w0, hp[2]); fma2(acc1[2], w1, hp[2]);
            fma2(acc0[3], w0, hp[3]); fma2(acc1[3], w1, hp[3]);
            fma2(acc0[4], w0, hp[4]); fma2(acc1[4], w1, hp[4]);
        }
    }
    __syncthreads();
    if (cq == 6){ den_s[2*rg] = up2(acc0[3]).x; den_s[2*rg+1] = up2(acc1[3]).x; }
    __syncthreads();
    float inv0 = 1.f/den_s[2*rg], inv1 = 1.f/den_s[2*rg+1];
    float* o0 = outp + (size_t)(row0 + 2*rg)*os + head*66;
    float* o1 = o0 + os;
#pragma unroll
    for (int q = 0; q < 5; q++){
        int c = cq*10 + 2*q;
        float2 a = up2(acc0[q]), b = up2(acc1[q]);
        if (c < 66){
            float v0 = a.x*inv0; o0[c] = fmaxf(v0, 0.01f*v0);
            float v1 = b.x*inv1; o1[c] = fmaxf(v1, 0.01f*v1);
        }
        if (c+1 < 66){
            float v0 = a.y*inv0; o0[c+1] = fmaxf(v0, 0.01f*v0);
            float v1 = b.y*inv1; o1[c+1] = fmaxf(v1, 0.01f*v1);
        }
    }
}

// value = sigmoid(sub @ g1_W + b); r scales hx into x2 cols 2..65; u saved.
__global__ void __launch_bounds__(128) gate1_kernel(const float* __restrict__ sub,
    const float* __restrict__ hx, const float* __restrict__ W, const float* __restrict__ b,
    float* __restrict__ xout, float* __restrict__ uout)
{
    __shared__ float xs[66];
    int i = blockIdx.x, c = threadIdx.x;
    for (int k = c; k < 66; k += 128) xs[k] = sub[i*66+k];
    __syncthreads();
    float a = b[c];
    for (int k = 0; k < 66; k++) a += xs[k]*W[k*128+c];
    float v = 1.f/(1.f + __expf(-a));
    if (c < 64) xout[i*66 + 2 + c] = v*hx[i*64+c];
    else uout[i*64 + c - 64] = v;
}

__global__ void __launch_bounds__(64) final_kernel(const float* __restrict__ sub,
    const float* __restrict__ hx, const float* __restrict__ u,
    const float* __restrict__ W, const float* __restrict__ b, float* __restrict__ out)
{
    __shared__ float xs[66];
    int i = blockIdx.x, c = threadIdx.x;
    for (int k = c; k < 66; k += 64) xs[k] = sub[i*66+k];
    __syncthreads();
    float a = b[c];
    for (int k = 0; k < 66; k++) a += xs[k]*W[k*64+c];
    float t = tanhf(a);
    float uu = u[i*64+c];
    out[i*64+c] = uu*hx[i*64+c] + (1.f - uu)*t;
}

static void run_subnet(const float* x, const float* W, const float* a1, const float* a2,
    const float* Wout, const float* ao1, const float* ao2,
    float* h, float* f1, float* f2, float* mx, unsigned* mask, float* hcat, float* sub)
{
    proj_kernel<<<dim3(64,4), 256>>>(x, 66, W, a1, a2, h, f1, f2);
    rowmax_kernel<<<512, 256>>>(f2, mask, mx, 4);
    agg_kernel<<<dim3(64,1,4), 256>>>(h, f1, f2, mx, mask, hcat, 264);
    proj_kernel<<<dim3(64,1), 256>>>(hcat, 264, Wout, ao1, ao2, h, f1, f2);
    rowmax_kernel<<<512, 256>>>(f2, mask, mx, 1);
    agg_kernel<<<dim3(64,1,1), 256>>>(h, f1, f2, mx, mask, sub, 66);
}

extern "C" void kernel_launch(void* const* d_in, const int* in_sizes, int n_in,
                              void* d_out, int out_size)
{
    const float* inputs = (const float*)d_in[0];
    const float* hx     = (const float*)d_in[1];
    const int*   adj    = (const int*)d_in[2];
    const float* m1_W   = (const float*)d_in[3];
    const float* m1_a1  = (const float*)d_in[4];
    const float* m1_a2  = (const float*)d_in[5];
    const float* m1_Wo  = (const float*)d_in[6];
    const float* m1_ao1 = (const float*)d_in[7];
    const float* m1_ao2 = (const float*)d_in[8];
    const float* m2_W   = (const float*)d_in[9];
    const float* m2_a1  = (const float*)d_in[10];
    const float* m2_a2  = (const float*)d_in[11];
    const float* m2_Wo  = (const float*)d_in[12];
    const float* m2_ao1 = (const float*)d_in[13];
    const float* m2_ao2 = (const float*)d_in[14];
    const float* g1_W   = (const float*)d_in[15];
    const float* g1_b   = (const float*)d_in[16];
    const float* g2_W   = (const float*)d_in[17];
    const float* g2_b   = (const float*)d_in[18];

    void *px,*ph,*pf1,*pf2,*pmx,*phcat,*psub,*pu,*pmask;
    cudaGetSymbolAddress(&px, g_x);
    cudaGetSymbolAddress(&ph, g_h);
    cudaGetSymbolAddress(&pf1, g_f1);
    cudaGetSymbolAddress(&pf2, g_f2);
    cudaGetSymbolAddress(&pmx, g_mx);
    cudaGetSymbolAddress(&phcat, g_hcat);
    cudaGetSymbolAddress(&psub, g_sub);
    cudaGetSymbolAddress(&pu, g_u);
    cudaGetSymbolAddress(&pmask, g_mask);
    float *x=(float*)px, *h=(float*)ph, *f1=(float*)pf1, *f2=(float*)pf2, *mx=(float*)pmx;
    float *hcat=(float*)phcat, *sub=(float*)psub, *u=(float*)pu;
    unsigned* mask = (unsigned*)pmask;

    pack_mask_kernel<<<2048, 256>>>(adj, mask);
    build_x1_kernel<<<(NN*66+255)/256, 256>>>(inputs, hx, x);
    run_subnet(x, m1_W, m1_a1, m1_a2, m1_Wo, m1_ao1, m1_ao2, h, f1, f2, mx, mask, hcat, sub);
    gate1_kernel<<<NN, 128>>>(sub, hx, g1_W, g1_b, x, u);
    run_subnet(x, m2_W, m2_a1, m2_a2, m2_Wo, m2_ao1, m2_ao2, h, f1, f2, mx, mask, hcat, sub);
    final_kernel<<<NN, 64>>>(sub, hx, u, g2_W, g2_b, (float*)d_out);
}